// round 11
// baseline (speedup 1.0000x reference)
#include <cuda_runtime.h>
#include <cuda_fp16.h>

#define BB 4
#define AA 512
#define DD 729
#define HH 512
#define WW 512

// Batch-AoS fp16 buffer: for each (angle a, det index i), 16 bytes =
// 4 batches x (v[i], v[i+1]-v[i]) as half2. One LDG.128 fetches all 4
// batches; interp = v0 + delta*f via one HFMA2 with weight (1, f).
__device__ __align__(16) __half2 g_pairs[AA * DD * BB];

// Pair-packed trig staging buffer: for angle pair p (angles 2p, 2p+1):
// (c0, c1, s0, s1) with c = cos/dsp, s = sin/dsp. Copied into constant.
__device__ __align__(16) float g_trig4[AA * 2];
__constant__ __align__(16) float4 c_trig[AA / 2];  // 4 KB

// One thread per (a, i). First 512 threads also build the trig table.
__global__ void build_pairs_kernel(const float* __restrict__ sino,
                                   const float* __restrict__ traj,
                                   const float* __restrict__ det_sp) {
    int idx = blockIdx.x * blockDim.x + threadIdx.x;  // idx = a*DD + i
    if (idx < AA) {
        float inv = 1.0f / det_sp[0];
        float th = traj[idx];
        int p = idx >> 1, j = idx & 1;
        g_trig4[p * 4 + j]     = cosf(th) * inv;
        g_trig4[p * 4 + 2 + j] = sinf(th) * inv;
    }
    const int total = AA * DD;
    if (idx >= total) return;
    int i = idx % DD;
    bool has_next = (i < DD - 1);

    uint4 out;
    unsigned* po = (unsigned*)&out;
#pragma unroll
    for (int b = 0; b < BB; ++b) {
        const float* p = sino + (size_t)b * (AA * DD) + idx;
        float v0 = p[0];
        float v1 = has_next ? p[1] : 0.0f;
        __half2 h = __floats2half2_rn(v0, v1 - v0);  // (v0, delta)
        po[b] = *(unsigned*)&h;
    }
    ((uint4*)g_pairs)[idx] = out;
}

// Packed fp32x2 helpers (ptxas never auto-fuses; lane-wise bit-identical
// to scalar fma.rn so numerics match the scalar version exactly).
__device__ __forceinline__ unsigned long long pk2(float lo, float hi) {
    unsigned long long v;
    asm("mov.b64 %0, {%1, %2};" : "=l"(v) : "f"(lo), "f"(hi));
    return v;
}
__device__ __forceinline__ void upk2(unsigned long long v, float& lo, float& hi) {
    asm("mov.b64 {%0, %1}, %2;" : "=f"(lo), "=f"(hi) : "l"(v));
}
__device__ __forceinline__ unsigned long long fma2(unsigned long long a,
                                                   unsigned long long b,
                                                   unsigned long long c) {
    unsigned long long d;
    asm("fma.rn.f32x2 %0, %1, %2, %3;" : "=l"(d) : "l"(a), "l"(b), "l"(c));
    return d;
}

// 256 threads/block over a 16x16 pixel tile; each WARP covers 8(x) x 4(y)
// pixels. Grid (32,32)=1024 blocks. Trig comes from constant memory
// (uniform-pipe loads; no smem, no LDS contention with the gathers).
// Packed fp16 interp (HFMA2), flushed to fp32 every FLUSH=4 angles via
// HADD + cvt. launch_bounds(256,8) pins regs at 32.
#define FLUSH 4

__global__ __launch_bounds__(256, 8)
void backproject_kernel(const float* __restrict__ vol_origin,
                        const float* __restrict__ det_origin,
                        const float* __restrict__ vol_sp,
                        const float* __restrict__ det_sp,
                        float* __restrict__ out) {
    const int tid  = threadIdx.x;
    const int w    = tid >> 5;
    const int lane = tid & 31;
    const int lx   = lane & 7;
    const int ly   = lane >> 3;
    const int wx   = w & 1;
    const int wy   = w >> 1;

    const int x = blockIdx.x * 16 + wx * 8 + lx;
    const int y = blockIdx.y * 16 + wy * 4 + ly;

    const float xs = vol_origin[1] + (float)x * vol_sp[1];
    const float ys = vol_origin[0] + (float)y * vol_sp[0];
    const float K  = -det_origin[0] / det_sp[0];

    const unsigned long long xs2 = pk2(xs, xs);
    const unsigned long long ys2 = pk2(ys, ys);
    const unsigned long long K2  = pk2(K, K);

    float acc0 = 0.f, acc1 = 0.f, acc2 = 0.f, acc3 = 0.f;

    const uint4* __restrict__ base = (const uint4*)g_pairs;

#pragma unroll 2
    for (int ag = 0; ag < AA; ag += FLUSH) {
        const uint4* __restrict__ row = base + ag * DD;  // k*DD folds to imm

        // u for 4 angles via two packed FFMA2 chains (trig from constant).
        const float4 tA = c_trig[(ag >> 1)];
        const float4 tB = c_trig[(ag >> 1) + 1];
        const unsigned long long uA =
            fma2(xs2, pk2(tA.x, tA.y), fma2(ys2, pk2(tA.z, tA.w), K2));
        const unsigned long long uB =
            fma2(xs2, pk2(tB.x, tB.y), fma2(ys2, pk2(tB.z, tB.w), K2));
        float u[4];
        upk2(uA, u[0], u[1]);
        upk2(uB, u[2], u[3]);

        __half2 h0 = __float2half2_rn(0.f);
        __half2 h1 = h0, h2 = h0, h3 = h0;

#pragma unroll
        for (int k = 0; k < FLUSH; ++k) {
            const float uu = u[k];
            // Geometry guarantees u in [2.7, 725.3]: trunc == floor.
            const float fl = truncf(uu);     // F2F.TRUNC (indep of F2I below)
            const int   i0 = (int)uu;        // F2I.TRUNC
            const float f  = uu - fl;
            const __half2 wgt = __floats2half2_rn(1.0f, f);

            const uint4 p = __ldg(row + k * DD + i0);

            h0 = __hfma2(*(const __half2*)&p.x, wgt, h0);
            h1 = __hfma2(*(const __half2*)&p.y, wgt, h1);
            h2 = __hfma2(*(const __half2*)&p.z, wgt, h2);
            h3 = __hfma2(*(const __half2*)&p.w, wgt, h3);
        }
        // Cheap flush: fp16 lane-add + cvt + fadd per batch.
        acc0 += __half2float(__hadd(__low2half(h0), __high2half(h0)));
        acc1 += __half2float(__hadd(__low2half(h1), __high2half(h1)));
        acc2 += __half2float(__hadd(__low2half(h2), __high2half(h2)));
        acc3 += __half2float(__hadd(__low2half(h3), __high2half(h3)));
    }

    const size_t px = (size_t)y * WW + x;
    out[px]                       = acc0;
    out[px + (size_t)HH * WW]     = acc1;
    out[px + (size_t)2 * HH * WW] = acc2;
    out[px + (size_t)3 * HH * WW] = acc3;
}

extern "C" void kernel_launch(void* const* d_in, const int* in_sizes, int n_in,
                              void* d_out, int out_size) {
    const float* sino       = (const float*)d_in[0];
    const float* vol_origin = (const float*)d_in[2];
    const float* det_origin = (const float*)d_in[3];
    const float* vol_sp     = (const float*)d_in[4];
    const float* det_sp     = (const float*)d_in[5];
    const float* traj       = (const float*)d_in[6];
    float* out = (float*)d_out;

    const int total = AA * DD;
    build_pairs_kernel<<<(total + 255) / 256, 256>>>(sino, traj, det_sp);

    // Stage trig into constant memory (D2D async memcpy: capturable).
    void* trig_src = nullptr;
    cudaGetSymbolAddress(&trig_src, g_trig4);
    cudaMemcpyToSymbolAsync(c_trig, trig_src, sizeof(float) * AA * 2, 0,
                            cudaMemcpyDeviceToDevice, 0);

    dim3 blk(256);
    dim3 grd(WW / 16, HH / 16);
    backproject_kernel<<<grd, blk>>>(vol_origin, det_origin, vol_sp, det_sp, out);
}